// round 5
// baseline (speedup 1.0000x reference)
#include <cuda_runtime.h>
#include <math.h>

// PyTorchCG: BS=64, N=1024, maxiter derived from out_size.
#define CG_N  1024
#define CG_BS 64
#define TS    128                 // symmetric tile size
#define NT    (CG_N / TS)         // 8 tiles per dim
#define NPAIR (NT * (NT + 1) / 2) // 36 unique tile pairs
#define TILE_F  (TS * TS)
#define TILE_F4 (TILE_F / 4)

// Persistent CG state (no allocs -> __device__ globals; all zero-initialized).
__device__ float    g_r  [CG_BS * CG_N];
__device__ float    g_p  [CG_BS * CG_N];
__device__ float    g_Ap [CG_BS * CG_N];
__device__ float    g_d  [CG_BS * CG_N];   // diag(M_inv)
__device__ float    g_rz [CG_BS];
__device__ float    g_pap[CG_BS];
__device__ unsigned g_done[CG_BS];         // per-batch arrival counter (self-resetting)
// Packed upper-triangle tiles: [b][pair][128x128] contiguous (144 MB scratch).
__device__ __align__(16) float g_pack[(size_t)CG_BS * NPAIR * TILE_F];

__device__ __forceinline__ int tri_off(int bi) { return bi * NT - (bi * (bi - 1)) / 2; }

// ---------------------------------------------------------------------------
// Pack upper-triangle tiles of A contiguously + extract diag(M_inv).
// Reads A row-contiguous (streaming).  grid=(N/8,BS), block=256.
// ---------------------------------------------------------------------------
__global__ void __launch_bounds__(256) k_pack(const float* __restrict__ A,
                                              const float* __restrict__ Minv)
{
    const int b    = blockIdx.y;
    const int warp = threadIdx.x >> 5;
    const int lane = threadIdx.x & 31;
    const int row  = (blockIdx.x << 3) + warp;     // 0..1023
    const int bi   = row >> 7;
    const int rloc = row & (TS - 1);

    const float4* Arow =
        reinterpret_cast<const float4*>(A + ((size_t)b * CG_N + row) * CG_N);

    for (int k = bi; k < NT; ++k) {
        float4 a = Arow[lane + 32 * k];
        const int li = tri_off(bi) + (k - bi);
        reinterpret_cast<float4*>(g_pack)
            [((size_t)b * NPAIR + li) * TILE_F4 + rloc * 32 + lane] = a;
    }
    if (lane == 0)
        g_d[(size_t)b * CG_N + row] =
            Minv[(size_t)b * CG_N * CG_N + (size_t)row * CG_N + row];
}

// ---------------------------------------------------------------------------
// Zero accumulators before the first matvec (defensive; consumers re-zero).
// ---------------------------------------------------------------------------
__global__ void k_zero()
{
    const int b = blockIdx.x, tid = threadIdx.x;
    reinterpret_cast<float4*>(g_Ap + (size_t)b * CG_N)[tid] =
        make_float4(0.f, 0.f, 0.f, 0.f);
    if (tid == 0) { g_pap[b] = 0.f; g_done[b] = 0u; }
}

// ---------------------------------------------------------------------------
// Deterministic block-wide sum over 256 threads.
// ---------------------------------------------------------------------------
__device__ __forceinline__ float block_sum(float v, float* sbuf)
{
    const int tid = threadIdx.x;
#pragma unroll
    for (int off = 16; off; off >>= 1)
        v += __shfl_xor_sync(0xffffffffu, v, off);
    if ((tid & 31) == 0) sbuf[tid >> 5] = v;
    __syncthreads();
    if (tid < 8) {
        float w = sbuf[tid];
#pragma unroll
        for (int off = 4; off; off >>= 1)
            w += __shfl_xor_sync(0x000000ffu, w, off);
        if (tid == 0) sbuf[0] = w;
    }
    __syncthreads();
    float r = sbuf[0];
    __syncthreads();
    return r;
}

// ---------------------------------------------------------------------------
// Symmetric batched matvec on packed tiles + FUSED CG update (last-CTA-done).
// grid=(NPAIR, BS).  g_Ap/g_pap must be zero on entry; they (and g_done) are
// re-zeroed by the updater, keeping the graph replay-safe.
// do_update==0: matvec only (used for A@x0).
// ---------------------------------------------------------------------------
__global__ void __launch_bounds__(256) k_symmv(const float* __restrict__ v,
                                               float* __restrict__ out,
                                               int it, int ldout, int do_update)
{
    const int b   = blockIdx.y;
    const int tid = threadIdx.x;

    int li = blockIdx.x, bi = 0;
    while (li >= NT - bi) { li -= NT - bi; ++bi; }
    const int  bj   = bi + li;
    const bool diag = (bi == bj);

    __shared__ float spi[TS];
    __shared__ float spj[TS];
    __shared__ float sd[8][16][33];
    __shared__ float scol[8][TS];
    __shared__ float sbuf[8];
    __shared__ bool  is_last;

    const float* vb = (v != nullptr) ? (v + (size_t)b * CG_N)
                                     : (g_p + (size_t)b * CG_N);
    if (tid < TS / 4)
        reinterpret_cast<float4*>(spi)[tid] =
            reinterpret_cast<const float4*>(vb + bi * TS)[tid];
    else if (tid < TS / 2)
        reinterpret_cast<float4*>(spj)[tid - TS / 4] =
            reinterpret_cast<const float4*>(vb + bj * TS)[tid - TS / 4];
    __syncthreads();

    const int warp = tid >> 5;
    const int lane = tid & 31;

    const float4* T = reinterpret_cast<const float4*>(g_pack) +
                      ((size_t)b * NPAIR + blockIdx.x) * TILE_F4 +
                      (size_t)warp * 16 * 32;

    const float4 pj4 = reinterpret_cast<const float4*>(spj)[lane];
    float4 cacc = make_float4(0.f, 0.f, 0.f, 0.f);

    // two 8-deep independent contiguous LDG.128 batches per warp
    {
        float4 a[8];
#pragma unroll
        for (int k = 0; k < 8; ++k) a[k] = T[k * 32 + lane];
#pragma unroll
        for (int k = 0; k < 8; ++k) {
            sd[warp][k][lane] = a[k].x * pj4.x + a[k].y * pj4.y +
                                a[k].z * pj4.z + a[k].w * pj4.w;
            const float pir = spi[16 * warp + k];
            cacc.x += a[k].x * pir;  cacc.y += a[k].y * pir;
            cacc.z += a[k].z * pir;  cacc.w += a[k].w * pir;
        }
    }
    {
        float4 a[8];
#pragma unroll
        for (int k = 0; k < 8; ++k) a[k] = T[(k + 8) * 32 + lane];
#pragma unroll
        for (int k = 0; k < 8; ++k) {
            sd[warp][k + 8][lane] = a[k].x * pj4.x + a[k].y * pj4.y +
                                    a[k].z * pj4.z + a[k].w * pj4.w;
            const float pir = spi[16 * warp + 8 + k];
            cacc.x += a[k].x * pir;  cacc.y += a[k].y * pir;
            cacc.z += a[k].z * pir;  cacc.w += a[k].w * pir;
        }
    }

    if (!diag) {
        scol[warp][4 * lane + 0] = cacc.x;
        scol[warp][4 * lane + 1] = cacc.y;
        scol[warp][4 * lane + 2] = cacc.z;
        scol[warp][4 * lane + 3] = cacc.w;
    }
    __syncthreads();

    // row dots -> y_bi
    const int ri = tid >> 1;
    const int hi = tid & 1;
    float s = 0.f;
#pragma unroll
    for (int j = 0; j < 16; ++j)
        s += sd[ri >> 4][ri & 15][16 * hi + j];
    s += __shfl_xor_sync(0xffffffffu, s, 1);

    float pap_c = 0.f;
    if (hi == 0) {
        atomicAdd(&g_Ap[(size_t)b * CG_N + (size_t)bi * TS + ri], s);
        pap_c = s * spi[ri];
    }

    // transpose part -> y_bj
    if (!diag && tid < TS) {
        float cs = 0.f;
#pragma unroll
        for (int w = 0; w < 8; ++w) cs += scol[w][tid];
        atomicAdd(&g_Ap[(size_t)b * CG_N + (size_t)bj * TS + tid], cs);
    }

    // pAp block reduce -> g_pap
#pragma unroll
    for (int off = 16; off; off >>= 1)
        pap_c += __shfl_xor_sync(0xffffffffu, pap_c, off);
    if (lane == 0) sbuf[warp] = pap_c;
    __syncthreads();
    if (tid == 0) {
        float t = 0.f;
#pragma unroll
        for (int w = 0; w < 8; ++w) t += sbuf[w];
        atomicAdd(&g_pap[b], diag ? t : 2.f * t);
    }

    if (!do_update) return;

    // ---- last-CTA-done detection for batch b ----
    __threadfence();                       // release our atomics
    if (tid == 0) {
        unsigned n = atomicAdd(&g_done[b], 1u);
        is_last = (n == NPAIR - 1);
    }
    __syncthreads();
    if (!is_last) return;
    __threadfence();                       // acquire all CTAs' atomics

    // ---- fused CG update for batch b (one CTA, 256 threads) ----
    if (tid == 0) g_done[b] = 0u;

    const float rz_old = g_rz[b];
    const float alpha  = rz_old / g_pap[b];

    float pv[4], rv[4], dv[4];
    float rz_p = 0.f, rr_p = 0.f;
#pragma unroll
    for (int k = 0; k < 4; ++k) {
        const size_t i = (size_t)b * CG_N + tid + 256 * k;
        const float ap = g_Ap[i];
        g_Ap[i] = 0.f;                     // zero for next iteration
        pv[k] = g_p[i];
        dv[k] = g_d[i];
        rv[k] = g_r[i] - alpha * ap;
        g_r[i] = rv[k];
        const float zv = dv[k] * rv[k];
        rz_p += rv[k] * zv;
        rr_p += rv[k] * rv[k];
    }
    __syncthreads();                       // sbuf reuse hazard
    const float rz_new = block_sum(rz_p, sbuf);
    const float rr     = block_sum(rr_p, sbuf);
    const float beta   = rz_new / rz_old;

#pragma unroll
    for (int k = 0; k < 4; ++k) {
        const size_t i = (size_t)b * CG_N + tid + 256 * k;
        g_p[i] = dv[k] * rv[k] + beta * pv[k];
    }

    if (tid == 0) {
        g_rz[b]  = rz_new;
        g_pap[b] = 0.f;
        out[(size_t)b * ldout + it + 1] = sqrtf(rr);
    }
}

// ---------------------------------------------------------------------------
// Init: r0 = b - A@x0 (g_Ap), z0 = d*r0, p0 = z0, rz0, ||r0||.
// Re-zeroes g_Ap / g_pap.  grid=BS, block=256.
// ---------------------------------------------------------------------------
__global__ void k_init(const float* __restrict__ bvec,
                       float* __restrict__ out, int ldout)
{
    __shared__ float sbuf[8];
    const int b   = blockIdx.x;
    const int tid = threadIdx.x;

    float rz_p = 0.f, rr_p = 0.f;
#pragma unroll
    for (int k = 0; k < CG_N / 256; ++k) {
        const int    i  = tid + 256 * k;
        const size_t gi = (size_t)b * CG_N + i;
        float dv = g_d[gi];
        float rv = bvec[gi] - g_Ap[gi];
        g_Ap[gi] = 0.f;
        float zv = dv * rv;
        g_r[gi] = rv;
        g_p[gi] = zv;
        rz_p += rv * zv;
        rr_p += rv * rv;
    }
    float rz = block_sum(rz_p, sbuf);
    float rr = block_sum(rr_p, sbuf);
    if (tid == 0) {
        g_rz[b]  = rz;
        g_pap[b] = 0.f;
        out[(size_t)b * ldout] = sqrtf(rr);
    }
}

// ---------------------------------------------------------------------------
// kernel_launch: 54 graph-capturable launches.
// ---------------------------------------------------------------------------
extern "C" void kernel_launch(void* const* d_in, const int* in_sizes, int n_in,
                              void* d_out, int out_size)
{
    const float* A    = (const float*)d_in[0];
    const float* bvec = (const float*)d_in[1];
    const float* x0   = (const float*)d_in[2];
    const float* Minv = (const float*)d_in[3];
    float* out        = (float*)d_out;

    const int ldout   = out_size / CG_BS;   // maxiter + 1
    const int maxiter = ldout - 1;

    dim3 grid_pk(CG_N / 8, CG_BS);
    dim3 grid_mv(NPAIR, CG_BS);             // 36 x 64 = 2304 CTAs

    k_pack<<<grid_pk, 256>>>(A, Minv);
    k_zero<<<CG_BS, 256>>>();
    k_symmv<<<grid_mv, 256>>>(x0, out, 0, ldout, 0);   // g_Ap = A @ x0
    k_init <<<CG_BS, 256>>>(bvec, out, ldout);

    for (int it = 0; it < maxiter; ++it)
        k_symmv<<<grid_mv, 256>>>(nullptr, out, it, ldout, 1);
}